// round 15
// baseline (speedup 1.0000x reference)
#include <cuda_runtime.h>
#include <cuda_bf16.h>

// ---------------- problem constants ----------------
#define N_  100000
#define E_  3200000
#define D_  128
#define G_  64
#define C_  4
#define PAD 128                      // padded CSR row capacity (max deg ~60)
#define TILES_ 782                   // ceil(N/128)

// ---------------- static device scratch (zero-initialized at module load) ----
__device__ __nv_bfloat16 g_ah[N_ * D_];   // hsum hi
__device__ __nv_bfloat16 g_al[N_ * D_];   // hsum lo
__device__ float g_h   [N_ * D_];
__device__ int   g_cur [N_];              // slot counter == degree after scatter
__device__ int   g_csr [N_ * PAD];
__device__ float g_pooled[G_ * D_];
__device__ __nv_bfloat16 g_wh[6 * D_ * D_];
__device__ __nv_bfloat16 g_wl[6 * D_ * D_];

// ---------------- CSR build: single scatter pass into padded rows ----------------
__global__ void k_scatter(const int* __restrict__ ei) {
    int e = blockIdx.x * blockDim.x + threadIdx.x;
    if (e < E_) {
        int d    = ei[E_ + e];                    // dst
        int slot = atomicAdd(&g_cur[d], 1);
        g_csr[d * PAD + slot] = ei[e];            // src
    }
}

// ---------------- SpMM: hsum = h + sum_{j->i} h_j -> bf16 hi/lo ----------------
// Constant-trip inner loop: lanes beyond deg gather the node's OWN row (L1-hot),
// exact correction applied afterward. 8 independent LDG.128 in flight per group.
__global__ void __launch_bounds__(256) k_spmm(const float* __restrict__ h) {
    int node = (blockIdx.x * blockDim.x + threadIdx.x) >> 5;
    if (node >= N_) return;
    int lane = threadIdx.x & 31;
    const float4* h4 = (const float4*)h;
    const float4 self = h4[node * 32 + lane];
    int deg = g_cur[node];
    const int* row = g_csr + node * PAD;
    int nb = (deg + 31) >> 5;                     // 32-batches

    float4 a0 = make_float4(0.f, 0.f, 0.f, 0.f);
    float4 a1 = make_float4(0.f, 0.f, 0.f, 0.f);
    float4 a2 = make_float4(0.f, 0.f, 0.f, 0.f);
    float4 a3 = make_float4(0.f, 0.f, 0.f, 0.f);

    for (int b = 0; b < nb; b++) {
        int e = b * 32;
        int idx = node;                           // default: self row (hot)
        if (e + lane < deg) idx = row[e + lane];
        #pragma unroll
        for (int half = 0; half < 2; half++) {
            int n0 = __shfl_sync(0xffffffffu, idx, half * 16 + 0);
            int n1 = __shfl_sync(0xffffffffu, idx, half * 16 + 1);
            int n2 = __shfl_sync(0xffffffffu, idx, half * 16 + 2);
            int n3 = __shfl_sync(0xffffffffu, idx, half * 16 + 3);
            int n4 = __shfl_sync(0xffffffffu, idx, half * 16 + 4);
            int n5 = __shfl_sync(0xffffffffu, idx, half * 16 + 5);
            int n6 = __shfl_sync(0xffffffffu, idx, half * 16 + 6);
            int n7 = __shfl_sync(0xffffffffu, idx, half * 16 + 7);
            float4 v0 = h4[n0 * 32 + lane];
            float4 v1 = h4[n1 * 32 + lane];
            float4 v2 = h4[n2 * 32 + lane];
            float4 v3 = h4[n3 * 32 + lane];
            float4 v4 = h4[n4 * 32 + lane];
            float4 v5 = h4[n5 * 32 + lane];
            float4 v6 = h4[n6 * 32 + lane];
            float4 v7 = h4[n7 * 32 + lane];
            a0.x += v0.x; a0.y += v0.y; a0.z += v0.z; a0.w += v0.w;
            a1.x += v1.x; a1.y += v1.y; a1.z += v1.z; a1.w += v1.w;
            a2.x += v2.x; a2.y += v2.y; a2.z += v2.z; a2.w += v2.w;
            a3.x += v3.x; a3.y += v3.y; a3.z += v3.z; a3.w += v3.w;
            a0.x += v4.x; a0.y += v4.y; a0.z += v4.z; a0.w += v4.w;
            a1.x += v5.x; a1.y += v5.y; a1.z += v5.z; a1.w += v5.w;
            a2.x += v6.x; a2.y += v6.y; a2.z += v6.z; a2.w += v6.w;
            a3.x += v7.x; a3.y += v7.y; a3.z += v7.z; a3.w += v7.w;
            int n8  = __shfl_sync(0xffffffffu, idx, half * 16 + 8);
            int n9  = __shfl_sync(0xffffffffu, idx, half * 16 + 9);
            int n10 = __shfl_sync(0xffffffffu, idx, half * 16 + 10);
            int n11 = __shfl_sync(0xffffffffu, idx, half * 16 + 11);
            int n12 = __shfl_sync(0xffffffffu, idx, half * 16 + 12);
            int n13 = __shfl_sync(0xffffffffu, idx, half * 16 + 13);
            int n14 = __shfl_sync(0xffffffffu, idx, half * 16 + 14);
            int n15 = __shfl_sync(0xffffffffu, idx, half * 16 + 15);
            v0 = h4[n8  * 32 + lane];
            v1 = h4[n9  * 32 + lane];
            v2 = h4[n10 * 32 + lane];
            v3 = h4[n11 * 32 + lane];
            v4 = h4[n12 * 32 + lane];
            v5 = h4[n13 * 32 + lane];
            v6 = h4[n14 * 32 + lane];
            v7 = h4[n15 * 32 + lane];
            a0.x += v0.x; a0.y += v0.y; a0.z += v0.z; a0.w += v0.w;
            a1.x += v1.x; a1.y += v1.y; a1.z += v1.z; a1.w += v1.w;
            a2.x += v2.x; a2.y += v2.y; a2.z += v2.z; a2.w += v2.w;
            a3.x += v3.x; a3.y += v3.y; a3.z += v3.z; a3.w += v3.w;
            a0.x += v4.x; a0.y += v4.y; a0.z += v4.z; a0.w += v4.w;
            a1.x += v5.x; a1.y += v5.y; a1.z += v5.z; a1.w += v5.w;
            a2.x += v6.x; a2.y += v6.y; a2.z += v6.z; a2.w += v6.w;
            a3.x += v7.x; a3.y += v7.y; a3.z += v7.z; a3.w += v7.w;
        }
    }
    // total currently includes (nb*32 - deg) extra copies of self; want self + neighbors.
    float k = (float)(nb * 32 - deg - 1);         // subtract (extra - 1) * self
    float4 acc;
    acc.x = a0.x + a1.x + a2.x + a3.x - k * self.x;
    acc.y = a0.y + a1.y + a2.y + a3.y - k * self.y;
    acc.z = a0.z + a1.z + a2.z + a3.z - k * self.z;
    acc.w = a0.w + a1.w + a2.w + a3.w - k * self.w;

    float f[4] = {acc.x, acc.y, acc.z, acc.w};
    __nv_bfloat162 hp[2], lp[2];
    #pragma unroll
    for (int j = 0; j < 2; j++) {
        __nv_bfloat16 h0 = __float2bfloat16(f[j * 2]);
        __nv_bfloat16 h1 = __float2bfloat16(f[j * 2 + 1]);
        hp[j] = __nv_bfloat162(h0, h1);
        lp[j] = __nv_bfloat162(__float2bfloat16(f[j * 2]     - __bfloat162float(h0)),
                               __float2bfloat16(f[j * 2 + 1] - __bfloat162float(h1)));
    }
    *(uint2*)&g_ah[node * D_ + lane * 4] = *(uint2*)hp;
    *(uint2*)&g_al[node * D_ + lane * 4] = *(uint2*)lp;
}

// ---------------- weight split/transpose: Wt_hi/Wt_lo[n][k] ----------------
__global__ void k_wsplit(const float* __restrict__ Ws, int base) {
    int l = base + blockIdx.x;
    const float* W = Ws + l * D_ * D_;
    __nv_bfloat16* wh = g_wh + l * D_ * D_;
    __nv_bfloat16* wl = g_wl + l * D_ * D_;
    for (int i = threadIdx.x; i < D_ * D_; i += blockDim.x) {
        int k = i >> 7, n = i & 127;
        float w = W[i];
        __nv_bfloat16 hi = __float2bfloat16(w);
        float r = w - __bfloat162float(hi);
        wh[n * D_ + k] = hi;
        wl[n * D_ + k] = __float2bfloat16(r);
    }
}

// ---------------- fused conv: (A @ W1 -> BN1/ReLU -> @ W2 -> BN2/ReLU) --------
#define WT_STRIDE 136
#define SM_W1H  0
#define SM_W1L  (1 * D_ * WT_STRIDE)
#define SM_W2H  (2 * D_ * WT_STRIDE)
#define SM_W2L  (3 * D_ * WT_STRIDE)
#define SM_AH   (4 * D_ * WT_STRIDE)
#define SM_AL   (5 * D_ * WT_STRIDE)
#define SM_HALVES (6 * D_ * WT_STRIDE)          // 104448 halves = 208896 B
#define SM_BYTES  (SM_HALVES * 2 + 4 * D_ * 4)  // 210944 B

__device__ __forceinline__ void mma16816(float* d, const unsigned* a,
                                         unsigned b0, unsigned b1) {
    asm volatile(
        "mma.sync.aligned.m16n8k16.row.col.f32.bf16.bf16.f32 "
        "{%0,%1,%2,%3},{%4,%5,%6,%7},{%8,%9},{%0,%1,%2,%3};\n"
        : "+f"(d[0]), "+f"(d[1]), "+f"(d[2]), "+f"(d[3])
        : "r"(a[0]), "r"(a[1]), "r"(a[2]), "r"(a[3]), "r"(b0), "r"(b1));
}

__device__ __forceinline__ void ldsm4(unsigned* r, unsigned addr) {
    asm volatile("ldmatrix.sync.aligned.m8n8.x4.shared.b16 {%0,%1,%2,%3}, [%4];\n"
                 : "=r"(r[0]), "=r"(r[1]), "=r"(r[2]), "=r"(r[3]) : "r"(addr));
}

__device__ __forceinline__ void cpasync16(unsigned dst, const void* src) {
    asm volatile("cp.async.ca.shared.global [%0], [%1], 16;\n"
                 :: "r"(dst), "l"(src));
}

__global__ void __launch_bounds__(512, 1) k_conv(
    const __nv_bfloat16* __restrict__ Agh,
    const __nv_bfloat16* __restrict__ Agl,
    const __nv_bfloat16* __restrict__ w1h, const __nv_bfloat16* __restrict__ w1l,
    const __nv_bfloat16* __restrict__ w2h, const __nv_bfloat16* __restrict__ w2l,
    const float* __restrict__ bias, const float* __restrict__ gamma,
    const float* __restrict__ beta, const float* __restrict__ mean,
    const float* __restrict__ var,
    float* __restrict__ OutF, int M)
{
    extern __shared__ __nv_bfloat16 sm[];
    float* s_scale1 = (float*)(sm + SM_HALVES);
    float* s_shift1 = s_scale1 + D_;
    float* s_scale2 = s_shift1 + D_;
    float* s_shift2 = s_scale2 + D_;

    const int tid  = threadIdx.x;
    const int lane = tid & 31;
    const int wid  = tid >> 5;
    const int warpRow = (wid >> 2) * 32;
    const int warpCol = (wid & 3) * 32;
    const int bx   = blockIdx.x;
    const int grid = gridDim.x;
    const unsigned smBase = (unsigned)__cvta_generic_to_shared(sm);

    const int nT = (bx < TILES_) ? ((TILES_ - bx) + grid - 1) / grid : 0;

    auto stage_tile = [&](int tile) {
        const int row0 = tile * 128;
        for (int i = tid; i < 2048; i += 512) {
            int r = i >> 4, q = i & 15;
            int gr = row0 + r; if (gr > M - 1) gr = M - 1;
            unsigned off = 2u * (r * WT_STRIDE + q * 8);
            cpasync16(smBase + 2u * SM_AH + off, Agh + gr * 128 + q * 8);
            cpasync16(smBase + 2u * SM_AL + off, Agl + gr * 128 + q * 8);
        }
        asm volatile("cp.async.commit_group;\n");
    };

    for (int i = tid; i < 2048; i += 512) {
        int r = i >> 4, q = i & 15;
        unsigned off = 2u * (r * WT_STRIDE + q * 8);
        cpasync16(smBase + 2u * SM_W1H + off, w1h + r * 128 + q * 8);
        cpasync16(smBase + 2u * SM_W1L + off, w1l + r * 128 + q * 8);
        cpasync16(smBase + 2u * SM_W2H + off, w2h + r * 128 + q * 8);
        cpasync16(smBase + 2u * SM_W2L + off, w2l + r * 128 + q * 8);
    }
    if (nT > 0) stage_tile(bx);

    if (tid < 128) {
        float sc = gamma[tid] * rsqrtf(var[tid] + 1e-5f);
        s_scale1[tid] = sc;
        s_shift1[tid] = (bias[tid] - mean[tid]) * sc + beta[tid];
    } else if (tid < 256) {
        int c = tid - 128;
        float sc = gamma[D_ + c] * rsqrtf(var[D_ + c] + 1e-5f);
        s_scale2[c] = sc;
        s_shift2[c] = (bias[D_ + c] - mean[D_ + c]) * sc + beta[D_ + c];
    }

    const int aRowSel = (lane & 7) + ((lane >> 3) & 1) * 8;
    const int aColSel = ((lane >> 4) & 1) * 8;
    const unsigned aBase = smBase + 2u * (SM_AH + (warpRow + aRowSel) * WT_STRIDE + aColSel);
    const unsigned ALO   = 2u * (SM_AL - SM_AH);
    const int bm = lane >> 3;
    const int bRowSel = ((bm >> 1) & 1) * 8 + (lane & 7);
    const int bColSel = (bm & 1) * 8;
    const unsigned b1Base = smBase + 2u * (SM_W1H + (warpCol + bRowSel) * WT_STRIDE + bColSel);
    const unsigned W2OFF  = 2u * (SM_W2H - SM_W1H);
    const unsigned WLO    = 2u * (SM_W1L - SM_W1H);

    float acc[2][4][4];

    for (int i = 0; i < nT; i++) {
        const int tile = bx + i * grid;
        const int row0 = tile * 128;

        asm volatile("cp.async.wait_group 0;\n");
        __syncthreads();

        #pragma unroll 1
        for (int pass = 0; pass < 2; pass++) {
            const unsigned bB = pass ? (b1Base + W2OFF) : b1Base;

            #pragma unroll
            for (int m = 0; m < 2; m++)
                #pragma unroll
                for (int n = 0; n < 4; n++)
                    #pragma unroll
                    for (int v = 0; v < 4; v++) acc[m][n][v] = 0.0f;

            #pragma unroll
            for (int kk = 0; kk < 128; kk += 16) {
                unsigned ah[2][4], al[2][4], bh[2][4], bl[2][4];
                #pragma unroll
                for (int mt = 0; mt < 2; mt++) {
                    unsigned ad = aBase + 2u * (mt * 16 * WT_STRIDE + kk);
                    ldsm4(ah[mt], ad);
                    ldsm4(al[mt], ad + ALO);
                }
                #pragma unroll
                for (int p = 0; p < 2; p++) {
                    unsigned bd = bB + 2u * (p * 16 * WT_STRIDE + kk);
                    ldsm4(bh[p], bd);
                    ldsm4(bl[p], bd + WLO);
                }
                #pragma unroll
                for (int p = 0; p < 2; p++)
                    #pragma unroll
                    for (int t2 = 0; t2 < 2; t2++) {
                        int nt = p * 2 + t2;
                        #pragma unroll
                        for (int mt = 0; mt < 2; mt++)
                            mma16816(acc[mt][nt], ah[mt], bh[p][t2 * 2], bh[p][t2 * 2 + 1]);
                    }
                #pragma unroll
                for (int p = 0; p < 2; p++)
                    #pragma unroll
                    for (int t2 = 0; t2 < 2; t2++) {
                        int nt = p * 2 + t2;
                        #pragma unroll
                        for (int mt = 0; mt < 2; mt++)
                            mma16816(acc[mt][nt], al[mt], bh[p][t2 * 2], bh[p][t2 * 2 + 1]);
                    }
                #pragma unroll
                for (int p = 0; p < 2; p++)
                    #pragma unroll
                    for (int t2 = 0; t2 < 2; t2++) {
                        int nt = p * 2 + t2;
                        #pragma unroll
                        for (int mt = 0; mt < 2; mt++)
                            mma16816(acc[mt][nt], ah[mt], bl[p][t2 * 2], bl[p][t2 * 2 + 1]);
                    }
            }
            __syncthreads();      // all A/inter reads complete

            if (pass == 0) {
                #pragma unroll
                for (int mt = 0; mt < 2; mt++)
                    #pragma unroll
                    for (int half = 0; half < 2; half++) {
                        int r = warpRow + mt * 16 + (lane >> 2) + half * 8;
                        #pragma unroll
                        for (int nt = 0; nt < 4; nt++) {
                            int c = warpCol + nt * 8 + (lane & 3) * 2;
                            float y0 = fmaxf(acc[mt][nt][half * 2]     * s_scale1[c]     + s_shift1[c],     0.f);
                            float y1 = fmaxf(acc[mt][nt][half * 2 + 1] * s_scale1[c + 1] + s_shift1[c + 1], 0.f);
                            __nv_bfloat16 h0 = __float2bfloat16(y0);
                            __nv_bfloat16 h1 = __float2bfloat16(y1);
                            __nv_bfloat162 hp(h0, h1);
                            __nv_bfloat162 lp(__float2bfloat16(y0 - __bfloat162float(h0)),
                                              __float2bfloat16(y1 - __bfloat162float(h1)));
                            *(unsigned*)(sm + SM_AH + r * WT_STRIDE + c) = *(unsigned*)&hp;
                            *(unsigned*)(sm + SM_AL + r * WT_STRIDE + c) = *(unsigned*)&lp;
                        }
                    }
                __syncthreads();
            } else {
                if (i + 1 < nT) stage_tile(bx + (i + 1) * grid);
                #pragma unroll
                for (int mt = 0; mt < 2; mt++)
                    #pragma unroll
                    for (int half = 0; half < 2; half++) {
                        int gr = row0 + warpRow + mt * 16 + (lane >> 2) + half * 8;
                        if (gr >= M) continue;
                        #pragma unroll
                        for (int nt = 0; nt < 4; nt++) {
                            int c = warpCol + nt * 8 + (lane & 3) * 2;
                            float2 o;
                            o.x = fmaxf(acc[mt][nt][half * 2]     * s_scale2[c]     + s_shift2[c],     0.f);
                            o.y = fmaxf(acc[mt][nt][half * 2 + 1] * s_scale2[c + 1] + s_shift2[c + 1], 0.f);
                            *(float2*)&OutF[gr * 128 + c] = o;
                        }
                    }
            }
        }
    }
}

// ---------------- zero cur/pooled (end of sequence; module init covers call #1) ----
__global__ void k_zerop() {
    int i = blockIdx.x * blockDim.x + threadIdx.x;
    if (i < N_) g_cur[i] = 0;
    if (i < G_ * D_) g_pooled[i] = 0.0f;
}

// ---------------- segment_max pool ----------------
__global__ void k_pool(const int* __restrict__ batch) {
    int t  = threadIdx.x;
    int n0 = blockIdx.x * 128;
    int n1 = n0 + 128; if (n1 > N_) n1 = N_;
    int curg = batch[n0];
    float m = 0.0f;
    for (int n = n0; n < n1; n++) {
        int g = batch[n];
        if (g != curg) {
            atomicMax((unsigned int*)&g_pooled[curg * D_ + t], __float_as_uint(m));
            m = 0.0f; curg = g;
        }
        m = fmaxf(m, g_h[n * D_ + t]);
    }
    atomicMax((unsigned int*)&g_pooled[curg * D_ + t], __float_as_uint(m));
}

// ---------------- classifier head + log_softmax ----------------
__global__ void k_head(const float* __restrict__ lw, const float* __restrict__ lb,
                       float* __restrict__ out) {
    int g = threadIdx.x;
    if (g >= G_) return;
    float lg[4] = {lb[0], lb[1], lb[2], lb[3]};
    for (int d = 0; d < D_; d++) {
        float p = g_pooled[g * D_ + d];
        #pragma unroll
        for (int c = 0; c < C_; c++) lg[c] += p * lw[d * C_ + c];
    }
    float mx = fmaxf(fmaxf(lg[0], lg[1]), fmaxf(lg[2], lg[3]));
    float s = 0.0f;
    #pragma unroll
    for (int c = 0; c < C_; c++) s += expf(lg[c] - mx);
    float ls = logf(s) + mx;
    #pragma unroll
    for (int c = 0; c < C_; c++) out[g * C_ + c] = lg[c] - ls;
}

// ---------------- host launcher ----------------
extern "C" void kernel_launch(void* const* d_in, const int* in_sizes, int n_in,
                              void* d_out, int out_size) {
    const float* x      = (const float*)d_in[0];
    const int*   ei     = (const int*)  d_in[1];
    const int*   batch  = (const int*)  d_in[2];
    const float* Ws     = (const float*)d_in[3];
    const float* bs     = (const float*)d_in[4];
    const float* gammas = (const float*)d_in[5];
    const float* betas  = (const float*)d_in[6];
    const float* means  = (const float*)d_in[7];
    const float* vars   = (const float*)d_in[8];
    const float* lw     = (const float*)d_in[9];
    const float* lb     = (const float*)d_in[10];
    float* out = (float*)d_out;

    float *h;
    __nv_bfloat16 *ah, *al, *wh, *wl;
    cudaGetSymbolAddress((void**)&h,  g_h);
    cudaGetSymbolAddress((void**)&ah, g_ah);
    cudaGetSymbolAddress((void**)&al, g_al);
    cudaGetSymbolAddress((void**)&wh, g_wh);
    cudaGetSymbolAddress((void**)&wl, g_wl);

    static int nsm = 0;
    if (nsm == 0) {
        cudaFuncSetAttribute(k_conv, cudaFuncAttributeMaxDynamicSharedMemorySize, SM_BYTES);
        cudaDeviceGetAttribute(&nsm, cudaDevAttrMultiProcessorCount, 0);
        if (nsm <= 0) nsm = 148;
    }

    const int NB = (N_ + 255) / 256;
    const int EB = (E_ + 255) / 256;
    const int SB = (N_ * 32 + 255) / 256;
    const int MB = (N_ + 127) / 128;

    // launch order puts the NEW k_spmm (layer 0) at index 3 -> profiled
    k_scatter<<<EB, 256>>>(ei);                      // 0 (cur==0 from zerop/init)
    k_wsplit<<<3, 256>>>(Ws, 0);                     // 1
    k_wsplit<<<3, 256>>>(Ws, 3);                     // 2

    for (int l = 0; l < 3; l++) {
        const float* hin = (l == 0) ? x : h;
        k_spmm<<<SB, 256>>>(hin);                    // 3 on l==0 -> profiled
        int i0 = l * 2;
        k_conv<<<nsm, 512, SM_BYTES>>>(ah, al,
                            wh + (i0 + 0) * D_ * D_, wl + (i0 + 0) * D_ * D_,
                            wh + (i0 + 1) * D_ * D_, wl + (i0 + 1) * D_ * D_,
                            bs + i0 * D_, gammas + i0 * D_, betas + i0 * D_,
                            means + i0 * D_, vars + i0 * D_,
                            h, N_);
    }

    k_zerop<<<NB, 256>>>();   // zero pooled for pool below + cur for next call
    k_pool<<<MB, 128>>>(batch);
    k_head<<<1, 64>>>(lw, lb, out);
}

// round 17
// speedup vs baseline: 1.0940x; 1.0940x over previous
#include <cuda_runtime.h>
#include <cuda_bf16.h>

// ---------------- problem constants ----------------
#define N_  100000
#define E_  3200000
#define D_  128
#define G_  64
#define C_  4
#define PAD 128                      // padded CSR row capacity (max deg ~60)
#define TILES_ 782                   // ceil(N/128)

// ---------------- static device scratch (zero-initialized at module load) ----
__device__ __nv_bfloat16 g_ah[N_ * D_];   // hsum hi
__device__ __nv_bfloat16 g_al[N_ * D_];   // hsum lo
__device__ float g_h   [N_ * D_];
__device__ int   g_cur [N_];              // slot counter == degree after scatter
__device__ int   g_csr [N_ * PAD];
__device__ float g_pooled[G_ * D_];
__device__ __nv_bfloat16 g_wh[6 * D_ * D_];
__device__ __nv_bfloat16 g_wl[6 * D_ * D_];

// ---------------- CSR build: single scatter pass into padded rows ----------------
__global__ void k_scatter(const int* __restrict__ ei) {
    int e = blockIdx.x * blockDim.x + threadIdx.x;
    if (e < E_) {
        int d    = ei[E_ + e];                    // dst
        int slot = atomicAdd(&g_cur[d], 1);
        g_csr[d * PAD + slot] = ei[e];            // src
    }
}

// ---------------- SpMM: hsum = h + sum_{j->i} h_j -> bf16 hi/lo ----------------
// Simple dynamic loop (proven fastest shape); occupancy forced to 8 CTAs/SM.
__global__ void __launch_bounds__(256, 8) k_spmm(const float* __restrict__ h) {
    int node = (blockIdx.x * blockDim.x + threadIdx.x) >> 5;
    if (node >= N_) return;
    int lane = threadIdx.x & 31;
    const float4* h4 = (const float4*)h;
    float4 acc = h4[node * 32 + lane];            // self term (eps = 0)
    int deg = g_cur[node];
    const int* row = g_csr + node * PAD;
    for (int e = 0; e < deg; e += 32) {
        int cnt = deg - e; if (cnt > 32) cnt = 32;
        int idx = 0;
        if (lane < cnt) idx = row[e + lane];
        for (int j = 0; j < cnt; j++) {
            int nbr = __shfl_sync(0xffffffffu, idx, j);
            float4 v = h4[nbr * 32 + lane];
            acc.x += v.x; acc.y += v.y; acc.z += v.z; acc.w += v.w;
        }
    }
    float f[4] = {acc.x, acc.y, acc.z, acc.w};
    __nv_bfloat162 hp[2], lp[2];
    #pragma unroll
    for (int j = 0; j < 2; j++) {
        __nv_bfloat16 h0 = __float2bfloat16(f[j * 2]);
        __nv_bfloat16 h1 = __float2bfloat16(f[j * 2 + 1]);
        hp[j] = __nv_bfloat162(h0, h1);
        lp[j] = __nv_bfloat162(__float2bfloat16(f[j * 2]     - __bfloat162float(h0)),
                               __float2bfloat16(f[j * 2 + 1] - __bfloat162float(h1)));
    }
    *(uint2*)&g_ah[node * D_ + lane * 4] = *(uint2*)hp;
    *(uint2*)&g_al[node * D_ + lane * 4] = *(uint2*)lp;
}

// ---------------- weight split/transpose: Wt_hi/Wt_lo[n][k] ----------------
__global__ void k_wsplit(const float* __restrict__ Ws, int base) {
    int l = base + blockIdx.x;
    const float* W = Ws + l * D_ * D_;
    __nv_bfloat16* wh = g_wh + l * D_ * D_;
    __nv_bfloat16* wl = g_wl + l * D_ * D_;
    for (int i = threadIdx.x; i < D_ * D_; i += blockDim.x) {
        int k = i >> 7, n = i & 127;
        float w = W[i];
        __nv_bfloat16 hi = __float2bfloat16(w);
        float r = w - __bfloat162float(hi);
        wh[n * D_ + k] = hi;
        wl[n * D_ + k] = __float2bfloat16(r);
    }
}

// ---------------- fused conv: (A @ W1 -> BN1/ReLU -> @ W2 -> BN2/ReLU) --------
#define WT_STRIDE 136
#define SM_W1H  0
#define SM_W1L  (1 * D_ * WT_STRIDE)
#define SM_W2H  (2 * D_ * WT_STRIDE)
#define SM_W2L  (3 * D_ * WT_STRIDE)
#define SM_AH   (4 * D_ * WT_STRIDE)
#define SM_AL   (5 * D_ * WT_STRIDE)
#define SM_HALVES (6 * D_ * WT_STRIDE)          // 104448 halves = 208896 B
#define SM_BYTES  (SM_HALVES * 2 + 4 * D_ * 4)  // 210944 B

__device__ __forceinline__ void mma16816(float* d, const unsigned* a,
                                         unsigned b0, unsigned b1) {
    asm volatile(
        "mma.sync.aligned.m16n8k16.row.col.f32.bf16.bf16.f32 "
        "{%0,%1,%2,%3},{%4,%5,%6,%7},{%8,%9},{%0,%1,%2,%3};\n"
        : "+f"(d[0]), "+f"(d[1]), "+f"(d[2]), "+f"(d[3])
        : "r"(a[0]), "r"(a[1]), "r"(a[2]), "r"(a[3]), "r"(b0), "r"(b1));
}

__device__ __forceinline__ void ldsm4(unsigned* r, unsigned addr) {
    asm volatile("ldmatrix.sync.aligned.m8n8.x4.shared.b16 {%0,%1,%2,%3}, [%4];\n"
                 : "=r"(r[0]), "=r"(r[1]), "=r"(r[2]), "=r"(r[3]) : "r"(addr));
}

__device__ __forceinline__ void cpasync16(unsigned dst, const void* src) {
    asm volatile("cp.async.ca.shared.global [%0], [%1], 16;\n"
                 :: "r"(dst), "l"(src));
}

__global__ void __launch_bounds__(512, 1) k_conv(
    const __nv_bfloat16* __restrict__ Agh,
    const __nv_bfloat16* __restrict__ Agl,
    const __nv_bfloat16* __restrict__ w1h, const __nv_bfloat16* __restrict__ w1l,
    const __nv_bfloat16* __restrict__ w2h, const __nv_bfloat16* __restrict__ w2l,
    const float* __restrict__ bias, const float* __restrict__ gamma,
    const float* __restrict__ beta, const float* __restrict__ mean,
    const float* __restrict__ var,
    float* __restrict__ OutF, int M)
{
    extern __shared__ __nv_bfloat16 sm[];
    float* s_scale1 = (float*)(sm + SM_HALVES);
    float* s_shift1 = s_scale1 + D_;
    float* s_scale2 = s_shift1 + D_;
    float* s_shift2 = s_scale2 + D_;

    const int tid  = threadIdx.x;
    const int lane = tid & 31;
    const int wid  = tid >> 5;
    const int warpRow = (wid >> 2) * 32;
    const int warpCol = (wid & 3) * 32;
    const int bx   = blockIdx.x;
    const int grid = gridDim.x;
    const unsigned smBase = (unsigned)__cvta_generic_to_shared(sm);

    const int nT = (bx < TILES_) ? ((TILES_ - bx) + grid - 1) / grid : 0;

    auto stage_tile = [&](int tile) {
        const int row0 = tile * 128;
        for (int i = tid; i < 2048; i += 512) {
            int r = i >> 4, q = i & 15;
            int gr = row0 + r; if (gr > M - 1) gr = M - 1;
            unsigned off = 2u * (r * WT_STRIDE + q * 8);
            cpasync16(smBase + 2u * SM_AH + off, Agh + gr * 128 + q * 8);
            cpasync16(smBase + 2u * SM_AL + off, Agl + gr * 128 + q * 8);
        }
        asm volatile("cp.async.commit_group;\n");
    };

    for (int i = tid; i < 2048; i += 512) {
        int r = i >> 4, q = i & 15;
        unsigned off = 2u * (r * WT_STRIDE + q * 8);
        cpasync16(smBase + 2u * SM_W1H + off, w1h + r * 128 + q * 8);
        cpasync16(smBase + 2u * SM_W1L + off, w1l + r * 128 + q * 8);
        cpasync16(smBase + 2u * SM_W2H + off, w2h + r * 128 + q * 8);
        cpasync16(smBase + 2u * SM_W2L + off, w2l + r * 128 + q * 8);
    }
    if (nT > 0) stage_tile(bx);

    if (tid < 128) {
        float sc = gamma[tid] * rsqrtf(var[tid] + 1e-5f);
        s_scale1[tid] = sc;
        s_shift1[tid] = (bias[tid] - mean[tid]) * sc + beta[tid];
    } else if (tid < 256) {
        int c = tid - 128;
        float sc = gamma[D_ + c] * rsqrtf(var[D_ + c] + 1e-5f);
        s_scale2[c] = sc;
        s_shift2[c] = (bias[D_ + c] - mean[D_ + c]) * sc + beta[D_ + c];
    }

    const int aRowSel = (lane & 7) + ((lane >> 3) & 1) * 8;
    const int aColSel = ((lane >> 4) & 1) * 8;
    const unsigned aBase = smBase + 2u * (SM_AH + (warpRow + aRowSel) * WT_STRIDE + aColSel);
    const unsigned ALO   = 2u * (SM_AL - SM_AH);
    const int bm = lane >> 3;
    const int bRowSel = ((bm >> 1) & 1) * 8 + (lane & 7);
    const int bColSel = (bm & 1) * 8;
    const unsigned b1Base = smBase + 2u * (SM_W1H + (warpCol + bRowSel) * WT_STRIDE + bColSel);
    const unsigned W2OFF  = 2u * (SM_W2H - SM_W1H);
    const unsigned WLO    = 2u * (SM_W1L - SM_W1H);

    float acc[2][4][4];

    for (int i = 0; i < nT; i++) {
        const int tile = bx + i * grid;
        const int row0 = tile * 128;

        asm volatile("cp.async.wait_group 0;\n");
        __syncthreads();

        #pragma unroll 1
        for (int pass = 0; pass < 2; pass++) {
            const unsigned bB = pass ? (b1Base + W2OFF) : b1Base;

            #pragma unroll
            for (int m = 0; m < 2; m++)
                #pragma unroll
                for (int n = 0; n < 4; n++)
                    #pragma unroll
                    for (int v = 0; v < 4; v++) acc[m][n][v] = 0.0f;

            #pragma unroll
            for (int kk = 0; kk < 128; kk += 16) {
                unsigned ah[2][4], al[2][4], bh[2][4], bl[2][4];
                #pragma unroll
                for (int mt = 0; mt < 2; mt++) {
                    unsigned ad = aBase + 2u * (mt * 16 * WT_STRIDE + kk);
                    ldsm4(ah[mt], ad);
                    ldsm4(al[mt], ad + ALO);
                }
                #pragma unroll
                for (int p = 0; p < 2; p++) {
                    unsigned bd = bB + 2u * (p * 16 * WT_STRIDE + kk);
                    ldsm4(bh[p], bd);
                    ldsm4(bl[p], bd + WLO);
                }
                #pragma unroll
                for (int p = 0; p < 2; p++)
                    #pragma unroll
                    for (int t2 = 0; t2 < 2; t2++) {
                        int nt = p * 2 + t2;
                        #pragma unroll
                        for (int mt = 0; mt < 2; mt++)
                            mma16816(acc[mt][nt], ah[mt], bh[p][t2 * 2], bh[p][t2 * 2 + 1]);
                    }
                #pragma unroll
                for (int p = 0; p < 2; p++)
                    #pragma unroll
                    for (int t2 = 0; t2 < 2; t2++) {
                        int nt = p * 2 + t2;
                        #pragma unroll
                        for (int mt = 0; mt < 2; mt++)
                            mma16816(acc[mt][nt], al[mt], bh[p][t2 * 2], bh[p][t2 * 2 + 1]);
                    }
                #pragma unroll
                for (int p = 0; p < 2; p++)
                    #pragma unroll
                    for (int t2 = 0; t2 < 2; t2++) {
                        int nt = p * 2 + t2;
                        #pragma unroll
                        for (int mt = 0; mt < 2; mt++)
                            mma16816(acc[mt][nt], ah[mt], bl[p][t2 * 2], bl[p][t2 * 2 + 1]);
                    }
            }
            __syncthreads();      // all A/inter reads complete

            if (pass == 0) {
                #pragma unroll
                for (int mt = 0; mt < 2; mt++)
                    #pragma unroll
                    for (int half = 0; half < 2; half++) {
                        int r = warpRow + mt * 16 + (lane >> 2) + half * 8;
                        #pragma unroll
                        for (int nt = 0; nt < 4; nt++) {
                            int c = warpCol + nt * 8 + (lane & 3) * 2;
                            float y0 = fmaxf(acc[mt][nt][half * 2]     * s_scale1[c]     + s_shift1[c],     0.f);
                            float y1 = fmaxf(acc[mt][nt][half * 2 + 1] * s_scale1[c + 1] + s_shift1[c + 1], 0.f);
                            __nv_bfloat16 h0 = __float2bfloat16(y0);
                            __nv_bfloat16 h1 = __float2bfloat16(y1);
                            __nv_bfloat162 hp(h0, h1);
                            __nv_bfloat162 lp(__float2bfloat16(y0 - __bfloat162float(h0)),
                                              __float2bfloat16(y1 - __bfloat162float(h1)));
                            *(unsigned*)(sm + SM_AH + r * WT_STRIDE + c) = *(unsigned*)&hp;
                            *(unsigned*)(sm + SM_AL + r * WT_STRIDE + c) = *(unsigned*)&lp;
                        }
                    }
                __syncthreads();
            } else {
                if (i + 1 < nT) stage_tile(bx + (i + 1) * grid);
                #pragma unroll
                for (int mt = 0; mt < 2; mt++)
                    #pragma unroll
                    for (int half = 0; half < 2; half++) {
                        int gr = row0 + warpRow + mt * 16 + (lane >> 2) + half * 8;
                        if (gr >= M) continue;
                        #pragma unroll
                        for (int nt = 0; nt < 4; nt++) {
                            int c = warpCol + nt * 8 + (lane & 3) * 2;
                            float2 o;
                            o.x = fmaxf(acc[mt][nt][half * 2]     * s_scale2[c]     + s_shift2[c],     0.f);
                            o.y = fmaxf(acc[mt][nt][half * 2 + 1] * s_scale2[c + 1] + s_shift2[c + 1], 0.f);
                            *(float2*)&OutF[gr * 128 + c] = o;
                        }
                    }
            }
        }
    }
}

// ---------------- zero cur/pooled (end of sequence; module init covers call #1) ----
__global__ void k_zerop() {
    int i = blockIdx.x * blockDim.x + threadIdx.x;
    if (i < N_) g_cur[i] = 0;
    if (i < G_ * D_) g_pooled[i] = 0.0f;
}

// ---------------- segment_max pool ----------------
__global__ void k_pool(const int* __restrict__ batch) {
    int t  = threadIdx.x;
    int n0 = blockIdx.x * 128;
    int n1 = n0 + 128; if (n1 > N_) n1 = N_;
    int curg = batch[n0];
    float m = 0.0f;
    for (int n = n0; n < n1; n++) {
        int g = batch[n];
        if (g != curg) {
            atomicMax((unsigned int*)&g_pooled[curg * D_ + t], __float_as_uint(m));
            m = 0.0f; curg = g;
        }
        m = fmaxf(m, g_h[n * D_ + t]);
    }
    atomicMax((unsigned int*)&g_pooled[curg * D_ + t], __float_as_uint(m));
}

// ---------------- classifier head + log_softmax ----------------
__global__ void k_head(const float* __restrict__ lw, const float* __restrict__ lb,
                       float* __restrict__ out) {
    int g = threadIdx.x;
    if (g >= G_) return;
    float lg[4] = {lb[0], lb[1], lb[2], lb[3]};
    for (int d = 0; d < D_; d++) {
        float p = g_pooled[g * D_ + d];
        #pragma unroll
        for (int c = 0; c < C_; c++) lg[c] += p * lw[d * C_ + c];
    }
    float mx = fmaxf(fmaxf(lg[0], lg[1]), fmaxf(lg[2], lg[3]));
    float s = 0.0f;
    #pragma unroll
    for (int c = 0; c < C_; c++) s += expf(lg[c] - mx);
    float ls = logf(s) + mx;
    #pragma unroll
    for (int c = 0; c < C_; c++) out[g * C_ + c] = lg[c] - ls;
}

// ---------------- host launcher ----------------
extern "C" void kernel_launch(void* const* d_in, const int* in_sizes, int n_in,
                              void* d_out, int out_size) {
    const float* x      = (const float*)d_in[0];
    const int*   ei     = (const int*)  d_in[1];
    const int*   batch  = (const int*)  d_in[2];
    const float* Ws     = (const float*)d_in[3];
    const float* bs     = (const float*)d_in[4];
    const float* gammas = (const float*)d_in[5];
    const float* betas  = (const float*)d_in[6];
    const float* means  = (const float*)d_in[7];
    const float* vars   = (const float*)d_in[8];
    const float* lw     = (const float*)d_in[9];
    const float* lb     = (const float*)d_in[10];
    float* out = (float*)d_out;

    float *h;
    __nv_bfloat16 *ah, *al, *wh, *wl;
    cudaGetSymbolAddress((void**)&h,  g_h);
    cudaGetSymbolAddress((void**)&ah, g_ah);
    cudaGetSymbolAddress((void**)&al, g_al);
    cudaGetSymbolAddress((void**)&wh, g_wh);
    cudaGetSymbolAddress((void**)&wl, g_wl);

    static int nsm = 0;
    if (nsm == 0) {
        cudaFuncSetAttribute(k_conv, cudaFuncAttributeMaxDynamicSharedMemorySize, SM_BYTES);
        cudaDeviceGetAttribute(&nsm, cudaDevAttrMultiProcessorCount, 0);
        if (nsm <= 0) nsm = 148;
    }

    const int NB = (N_ + 255) / 256;
    const int EB = (E_ + 255) / 256;
    const int SB = (N_ * 32 + 255) / 256;
    const int MB = (N_ + 127) / 128;

    // launch order puts k_spmm (layer 0) at index 3 -> profiled
    k_scatter<<<EB, 256>>>(ei);                      // 0 (cur==0 from zerop/init)
    k_wsplit<<<3, 256>>>(Ws, 0);                     // 1
    k_wsplit<<<3, 256>>>(Ws, 3);                     // 2

    for (int l = 0; l < 3; l++) {
        const float* hin = (l == 0) ? x : h;
        k_spmm<<<SB, 256>>>(hin);                    // 3 on l==0 -> profiled
        int i0 = l * 2;
        k_conv<<<nsm, 512, SM_BYTES>>>(ah, al,
                            wh + (i0 + 0) * D_ * D_, wl + (i0 + 0) * D_ * D_,
                            wh + (i0 + 1) * D_ * D_, wl + (i0 + 1) * D_ * D_,
                            bs + i0 * D_, gammas + i0 * D_, betas + i0 * D_,
                            means + i0 * D_, vars + i0 * D_,
                            h, N_);
    }

    k_zerop<<<NB, 256>>>();   // zero pooled for pool below + cur for next call
    k_pool<<<MB, 128>>>(batch);
    k_head<<<1, 64>>>(lw, lb, out);
}